// round 14
// baseline (speedup 1.0000x reference)
#include <cuda_runtime.h>
#include <cuda_fp16.h>
#include <cstdint>
#include <math.h>

#define BSZ   1024
#define TSEQ  64
#define IDIM  64
#define HDIM  1024
#define FUT   16
#define NSTEP (TSEQ + FUT)          // 80
#define G4H   (4 * HDIM)            // 4096
#define OUT_STRIDE (NSTEP * IDIM)   // 5120
#define NBATCH 63                   // deferred-head steps 0..62
#define HSLOTS 64                   // + slot 63 = step 79

typedef __half f16;

// ---------------- device scratch (static; no runtime allocation) ----------------
__device__ f16 g_wih1[G4H * IDIM];
__device__ f16 g_whh1[G4H * HDIM];
__device__ f16 g_wih2[G4H * HDIM];
__device__ f16 g_whh2[G4H * HDIM];
__device__ f16 g_wlinp[128 * HDIM];           // W_lin padded to 128 rows (64 real + 64 zero)
__device__ float g_bias1[G4H], g_bias2[G4H];
__device__ float g_blinp[128];                // b_lin padded
__device__ f16 g_x[BSZ * TSEQ * IDIM];
__device__ f16 g_h1[2][BSZ * HDIM];
__device__ f16 g_h2[2][BSZ * HDIM];           // hot double-buffer (recurrence operands)
__device__ f16 g_h2hist[(size_t)HSLOTS * BSZ * HDIM]; // shadow history (slots 0..62 = steps, 63 = step 79)
__device__ float g_c1[BSZ * HDIM], g_c2[BSZ * HDIM];
__device__ f16 g_fb[BSZ * IDIM];              // autoregressive feedback
__device__ float g_part[8 * BSZ * IDIM];      // inline head split-K partials

// ---------------- helpers ----------------
__device__ __forceinline__ uint32_t smem_u32(const void* p) {
    return (uint32_t)__cvta_generic_to_shared(p);
}
__device__ __forceinline__ void cp16(uint32_t dst, const void* src) {
    asm volatile("cp.async.cg.shared.global [%0], [%1], 16;\n" :: "r"(dst), "l"(src));
}
__device__ __forceinline__ void cp_commit() { asm volatile("cp.async.commit_group;\n"); }
template<int N> __device__ __forceinline__ void cp_wait() {
    asm volatile("cp.async.wait_group %0;\n" :: "n"(N));
}
__device__ __forceinline__ void ldsm4(uint32_t* r, uint32_t a) {
    asm volatile("ldmatrix.sync.aligned.m8n8.x4.shared.b16 {%0,%1,%2,%3}, [%4];"
        : "=r"(r[0]), "=r"(r[1]), "=r"(r[2]), "=r"(r[3]) : "r"(a));
}
__device__ __forceinline__ void mma16816(float* d, const uint32_t* a, uint32_t b0, uint32_t b1) {
    asm volatile("mma.sync.aligned.m16n8k16.row.col.f32.f16.f16.f32 "
        "{%0,%1,%2,%3}, {%4,%5,%6,%7}, {%8,%9}, {%0,%1,%2,%3};"
        : "+f"(d[0]), "+f"(d[1]), "+f"(d[2]), "+f"(d[3])
        : "r"(a[0]), "r"(a[1]), "r"(a[2]), "r"(a[3]), "r"(b0), "r"(b1));
}
#define SWZ(x) ((x) ^ (((x) >> 3) & 0x70))

__device__ __forceinline__ float sigm(float x) { return 1.f / (1.f + __expf(-x)); }
__device__ __forceinline__ float tanh_f(float x) { return 2.f / (1.f + __expf(-2.f * x)) - 1.f; }

// ---------------- prepass kernels (3 launches total) ----------------
#define QW1 (G4H * HDIM / 4)
#define QIH1 (G4H * IDIM / 4)
#define QLIN (128 * HDIM / 4)
__global__ void prepW(const float* __restrict__ whh1, const float* __restrict__ wih2,
                      const float* __restrict__ whh2, const float* __restrict__ wih1,
                      const float* __restrict__ wlin) {
    int q = blockIdx.x * blockDim.x + threadIdx.x;
    if (q < 3 * QW1) {
        const float* src = (q < QW1) ? whh1 : ((q < 2 * QW1) ? wih2 : whh2);
        f16* dst = (q < QW1) ? g_whh1 : ((q < 2 * QW1) ? g_wih2 : g_whh2);
        int e = (q % QW1) * 4;
        int n = e >> 10, k = e & 1023;
        int pn = ((n & 1023) << 2) | (n >> 10);
        float4 v = *(const float4*)(src + e);
        dst[(size_t)pn * 1024 + k + 0] = __float2half(v.x);
        dst[(size_t)pn * 1024 + k + 1] = __float2half(v.y);
        dst[(size_t)pn * 1024 + k + 2] = __float2half(v.z);
        dst[(size_t)pn * 1024 + k + 3] = __float2half(v.w);
    } else if (q < 3 * QW1 + QIH1) {
        int e = (q - 3 * QW1) * 4;
        int n = e >> 6, k = e & 63;
        int pn = ((n & 1023) << 2) | (n >> 10);
        float4 v = *(const float4*)(wih1 + e);
        g_wih1[(size_t)pn * 64 + k + 0] = __float2half(v.x);
        g_wih1[(size_t)pn * 64 + k + 1] = __float2half(v.y);
        g_wih1[(size_t)pn * 64 + k + 2] = __float2half(v.z);
        g_wih1[(size_t)pn * 64 + k + 3] = __float2half(v.w);
    } else {
        int e = (q - 3 * QW1 - QIH1) * 4;
        int row = e >> 10;
        if (row < 64) {
            float4 v = *(const float4*)(wlin + e);
            g_wlinp[e + 0] = __float2half(v.x);
            g_wlinp[e + 1] = __float2half(v.y);
            g_wlinp[e + 2] = __float2half(v.z);
            g_wlinp[e + 3] = __float2half(v.w);
        } else {
            f16 z = __float2half(0.f);
            g_wlinp[e + 0] = z; g_wlinp[e + 1] = z; g_wlinp[e + 2] = z; g_wlinp[e + 3] = z;
        }
    }
}
__global__ void prepX(const float* __restrict__ x) {
    size_t e = ((size_t)blockIdx.x * blockDim.x + threadIdx.x) * 4;
    float4 v = *(const float4*)(x + e);
    g_x[e + 0] = __float2half(v.x);
    g_x[e + 1] = __float2half(v.y);
    g_x[e + 2] = __float2half(v.z);
    g_x[e + 3] = __float2half(v.w);
}
__global__ void prepMisc(const float* b1a, const float* b1b,
                         const float* b2a, const float* b2b, const float* blin) {
    int i = blockIdx.x * blockDim.x + threadIdx.x;
    f16 z = __float2half(0.f);
    g_h1[0][i] = z; g_h2[0][i] = z;
    g_c1[i] = 0.f;  g_c2[i] = 0.f;
    if (i < BSZ * IDIM) g_fb[i] = z;
    if (i < G4H) {
        int pn = ((i & 1023) << 2) | (i >> 10);
        g_bias1[pn] = b1a[i] + b1b[i];
        g_bias2[pn] = b2a[i] + b2b[i];
    }
    if (i < 128) g_blinp[i] = (i < 64) ? blin[i] : 0.f;
}

// ---------------- main GEMM kernel (fp16 mma.sync, fused LSTM epilogue) ----------------
// C tile 128(M) x 128(N). Two A phases: nA chunks of (A1,W1), nB of (A2,W2).
// K-chunk = 64 fp16 (128B rows, SW128 swizzle). Single-barrier 3-stage pipeline.
#define STAGE 32768   // A 16K | W 16K

__global__ void __launch_bounds__(256, 2)
gemm_lstm(const f16* __restrict__ A1, int s1, int nA,
          const f16* __restrict__ A2, int s2, int nB,
          const f16* __restrict__ W1, int w1s,
          const f16* __restrict__ W2, int w2s,
          const float* __restrict__ bias,
          float* __restrict__ cbuf, f16* __restrict__ H,
          f16* __restrict__ hist)
{
    extern __shared__ __align__(1024) char smem[];
    const int tid = threadIdx.x;
    const int mBase = blockIdx.y * 128;
    const int nBase = blockIdx.x * 128;
    const uint32_t sb = smem_u32(smem);

    float* sbias = (float*)(smem + 3 * STAGE);
    if (tid < 128) sbias[tid] = bias[nBase + tid];

    const int C = nA + nB;

    auto load_chunk = [&](int c, int st) {
        const f16 *A, *W; int as, ws;
        if (c < nA) { A = A1 + c * 64; as = s1; W = W1 + c * 64; ws = w1s; }
        else        { int d = c - nA;
                      A = A2 + d * 64; as = s2; W = W2 + d * 64; ws = w2s; }
        uint32_t base = sb + st * STAGE;
        #pragma unroll
        for (int j = 0; j < 4; ++j) {
            int o = tid + j * 256; int row = o >> 3; int eo = (o & 7) * 8;
            uint32_t boff = SWZ(row * 128 + eo * 2);
            cp16(base + boff,         A + (size_t)(mBase + row) * as + eo);
            cp16(base + 16384 + boff, W + (size_t)(nBase + row) * ws + eo);
        }
        cp_commit();
    };

    const int w = tid >> 5, l = tid & 31;
    const int wm = (w & 3) * 32, wn = (w >> 2) * 64;

    float acc[2][8][4];
    #pragma unroll
    for (int mt = 0; mt < 2; ++mt)
        #pragma unroll
        for (int nt = 0; nt < 8; ++nt)
            #pragma unroll
            for (int j = 0; j < 4; ++j) acc[mt][nt][j] = 0.f;

    load_chunk(0, 0);
    if (C > 1) load_chunk(1, 1); else cp_commit();

    // precomputed swizzled base addresses; low 7 bits hold only bit 4, so
    // SWZ(base + ks*32) == SWZ(base) ^ (ks*32)
    uint32_t aB[2], wB[4];
    {
        const int aColSub = (l >> 4) << 4;
        #pragma unroll
        for (int mt = 0; mt < 2; ++mt)
            aB[mt] = SWZ((uint32_t)(((wm + mt * 16 + (l & 15)) << 7) + aColSub));
        const int wColSub = ((l >> 3) & 1) << 4;
        #pragma unroll
        for (int ng = 0; ng < 4; ++ng)
            wB[ng] = SWZ((uint32_t)(((wn + ng * 16 + (l & 7) + (((l >> 4) & 1) << 3)) << 7) + wColSub));
    }

    for (int c = 0; c < C; ++c) {
        const int st = c % 3;
        cp_wait<1>();
        __syncthreads();

        if (c + 2 < C) load_chunk(c + 2, (c + 2) % 3);
        else cp_commit();

        const uint32_t bA = sb + st * STAGE;
        const uint32_t bW = bA + 16384;

        #pragma unroll
        for (int ks = 0; ks < 4; ++ks) {
            const uint32_t kx = (uint32_t)(ks << 5);
            uint32_t af[2][4], wf[4][4];
            #pragma unroll
            for (int mt = 0; mt < 2; ++mt) ldsm4(af[mt], bA + (aB[mt] ^ kx));
            #pragma unroll
            for (int ng = 0; ng < 4; ++ng) ldsm4(wf[ng], bW + (wB[ng] ^ kx));
            #pragma unroll
            for (int mt = 0; mt < 2; ++mt) {
                #pragma unroll
                for (int ng = 0; ng < 4; ++ng) {
                    mma16816(acc[mt][ng * 2],     af[mt], wf[ng][0], wf[ng][1]);
                    mma16816(acc[mt][ng * 2 + 1], af[mt], wf[ng][2], wf[ng][3]);
                }
            }
        }
    }

    // ---------------- fused LSTM epilogue ----------------
    const int gr = l >> 2;
    const bool odd = l & 1;
    const int q = (l >> 1) & 1;

    #pragma unroll
    for (int mt = 0; mt < 2; ++mt) {
        #pragma unroll
        for (int nt = 0; nt < 8; ++nt) {
            float c0 = acc[mt][nt][0], c1 = acc[mt][nt][1];
            float c2 = acc[mt][nt][2], c3 = acc[mt][nt][3];
            float sx = odd ? c0 : c2;
            float sy = odd ? c1 : c3;
            float rx = __shfl_xor_sync(0xFFFFFFFFu, sx, 1);
            float ry = __shfl_xor_sync(0xFFFFFFFFu, sy, 1);
            float iv, fv, gv, ov;
            if (!odd) { iv = c0; fv = c1; gv = rx; ov = ry; }
            else      { iv = rx; fv = ry; gv = c2; ov = c3; }
            int nn  = wn + nt * 8 + q * 4;
            int row = mBase + wm + mt * 16 + gr + (odd ? 8 : 0);
            float xi = iv + sbias[nn + 0];
            float xf = fv + sbias[nn + 1];
            float xg = gv + sbias[nn + 2];
            float xo = ov + sbias[nn + 3];
            float gi = sigm(xi), gf = sigm(xf), gg = tanh_f(xg), go = sigm(xo);
            int unit = (nBase + nn) >> 2;
            size_t idx = (size_t)row * HDIM + unit;
            float cn = gf * cbuf[idx] + gi * gg;
            cbuf[idx] = cn;
            float hn = go * tanh_f(cn);
            f16 hv = __float2half(hn);
            H[idx] = hv;
            if (hist) hist[idx] = hv;
        }
    }
}

// ---------------- batched head kernel: tile 128(M) x 64(N), fp16 mma ----------------
// M = HSLOTS*1024 history rows; out[row & 1023, step, col], step = (row>>10), 63 -> 79.
#define HSTAGE 24576   // A 16K | W 8K

__global__ void __launch_bounds__(256, 2)
gemm_head(const f16* __restrict__ A, const f16* __restrict__ Wl,
          const float* __restrict__ bias, float* __restrict__ outp)
{
    extern __shared__ __align__(1024) char smem[];
    const int tid = threadIdx.x;
    const size_t mBase = (size_t)blockIdx.y * 128;
    const uint32_t sb = smem_u32(smem);

    float* sbias = (float*)(smem + 3 * HSTAGE);
    if (tid < 64) sbias[tid] = bias[tid];

    auto load_chunk = [&](int c, int st) {
        uint32_t base = sb + st * HSTAGE;
        const f16* Ap = A + c * 64;
        const f16* Wp = Wl + c * 64;
        #pragma unroll
        for (int j = 0; j < 4; ++j) {           // A: 128 rows x 128B
            int o = tid + j * 256; int row = o >> 3; int eo = (o & 7) * 8;
            uint32_t boff = SWZ(row * 128 + eo * 2);
            cp16(base + boff, Ap + (mBase + row) * (size_t)HDIM + eo);
        }
        #pragma unroll
        for (int j = 0; j < 2; ++j) {           // W: 64 rows x 128B
            int o = tid + j * 256; int row = o >> 3; int eo = (o & 7) * 8;
            uint32_t boff = SWZ(row * 128 + eo * 2);
            cp16(base + 16384 + boff, Wp + (size_t)row * HDIM + eo);
        }
        cp_commit();
    };

    // 8 warps = 4(m) x 2(n); warp tile 32 x 32
    const int w = tid >> 5, l = tid & 31;
    const int wm = (w & 3) * 32, wn = (w >> 2) * 32;

    float acc[2][4][4];
    #pragma unroll
    for (int mt = 0; mt < 2; ++mt)
        #pragma unroll
        for (int nt = 0; nt < 4; ++nt)
            #pragma unroll
            for (int j = 0; j < 4; ++j) acc[mt][nt][j] = 0.f;

    load_chunk(0, 0);
    load_chunk(1, 1);

    uint32_t aB[2], wB[2];
    {
        const int aColSub = (l >> 4) << 4;
        #pragma unroll
        for (int mt = 0; mt < 2; ++mt)
            aB[mt] = SWZ((uint32_t)(((wm + mt * 16 + (l & 15)) << 7) + aColSub));
        const int wColSub = ((l >> 3) & 1) << 4;
        #pragma unroll
        for (int ng = 0; ng < 2; ++ng)
            wB[ng] = SWZ((uint32_t)(((wn + ng * 16 + (l & 7) + (((l >> 4) & 1) << 3)) << 7) + wColSub));
    }

    const int C = 16;     // K = 1024
    for (int c = 0; c < C; ++c) {
        const int st = c % 3;
        cp_wait<1>();
        __syncthreads();

        if (c + 2 < C) load_chunk(c + 2, (c + 2) % 3);
        else cp_commit();

        const uint32_t bA = sb + st * HSTAGE;
        const uint32_t bW = bA + 16384;

        #pragma unroll
        for (int ks = 0; ks < 4; ++ks) {
            const uint32_t kx = (uint32_t)(ks << 5);
            uint32_t af[2][4], wf[2][4];
            #pragma unroll
            for (int mt = 0; mt < 2; ++mt) ldsm4(af[mt], bA + (aB[mt] ^ kx));
            #pragma unroll
            for (int ng = 0; ng < 2; ++ng) ldsm4(wf[ng], bW + (wB[ng] ^ kx));
            #pragma unroll
            for (int mt = 0; mt < 2; ++mt) {
                #pragma unroll
                for (int ng = 0; ng < 2; ++ng) {
                    mma16816(acc[mt][ng * 2],     af[mt], wf[ng][0], wf[ng][1]);
                    mma16816(acc[mt][ng * 2 + 1], af[mt], wf[ng][2], wf[ng][3]);
                }
            }
        }
    }

    // epilogue: scatter into out[batchrow, step, col]
    #pragma unroll
    for (int mt = 0; mt < 2; ++mt) {
        #pragma unroll
        for (int nt = 0; nt < 4; ++nt) {
            int col = wn + nt * 8 + 2 * (l & 3);
            size_t r0 = mBase + wm + mt * 16 + (l >> 2);
            size_t r1 = r0 + 8;
            int stp = (int)(r0 >> 10);
            if (stp == 63) stp = 79;             // slot 63 holds step 79
            float v0 = acc[mt][nt][0] + sbias[col];
            float v1 = acc[mt][nt][1] + sbias[col + 1];
            float v2 = acc[mt][nt][2] + sbias[col];
            float v3 = acc[mt][nt][3] + sbias[col + 1];
            float* p0 = outp + (r0 & 1023) * OUT_STRIDE + (size_t)stp * IDIM + col;
            float* p1 = outp + (r1 & 1023) * OUT_STRIDE + (size_t)stp * IDIM + col;
            p0[0] = v0; p0[1] = v1;
            p1[0] = v2; p1[1] = v3;
        }
    }
}

// ---------------- inline head (steps 63..78): fp32 split-K ----------------
__global__ __launch_bounds__(256)
void lin_stage1_kernel(const f16* __restrict__ H, const float* __restrict__ Wlin) {
    __shared__ float Hs[16][68];
    __shared__ float Ws[16][68];

    const int tid = threadIdx.x;
    const int mBase = blockIdx.x * 64;
    const int ks = blockIdx.y;
    const int kBeg = ks * 128;

    const int lr = tid >> 2;
    const int lc = (tid & 3) << 2;
    const int tx = tid & 15;
    const int ty = tid >> 4;

    float acc[4][4];
    #pragma unroll
    for (int i = 0; i < 4; ++i)
        #pragma unroll
        for (int j = 0; j < 4; ++j) acc[i][j] = 0.f;

    for (int k0 = kBeg; k0 < kBeg + 128; k0 += 16) {
        size_t hoff = (size_t)(mBase + lr) * HDIM + k0 + lc;
        const __half2* ph = (const __half2*)(H + hoff);
        float2 h0 = __half22float2(ph[0]);
        float2 h1 = __half22float2(ph[1]);
        Hs[lc + 0][lr] = h0.x; Hs[lc + 1][lr] = h0.y;
        Hs[lc + 2][lr] = h1.x; Hs[lc + 3][lr] = h1.y;
        float4 wv = *reinterpret_cast<const float4*>(&Wlin[(size_t)lr * HDIM + k0 + lc]);
        Ws[lc + 0][lr] = wv.x; Ws[lc + 1][lr] = wv.y;
        Ws[lc + 2][lr] = wv.z; Ws[lc + 3][lr] = wv.w;
        __syncthreads();

        #pragma unroll
        for (int kk = 0; kk < 16; ++kk) {
            float a[4], wv2[4];
            #pragma unroll
            for (int i = 0; i < 4; ++i) a[i] = Hs[kk][ty * 4 + i];
            #pragma unroll
            for (int j = 0; j < 4; ++j) wv2[j] = Ws[kk][tx * 4 + j];
            #pragma unroll
            for (int i = 0; i < 4; ++i)
                #pragma unroll
                for (int j = 0; j < 4; ++j)
                    acc[i][j] = fmaf(a[i], wv2[j], acc[i][j]);
        }
        __syncthreads();
    }

    #pragma unroll
    for (int i = 0; i < 4; ++i) {
        int m = mBase + ty * 4 + i;
        #pragma unroll
        for (int j = 0; j < 4; ++j) {
            int n = tx * 4 + j;
            g_part[(size_t)ks * (BSZ * IDIM) + m * IDIM + n] = acc[i][j];
        }
    }
}

__global__ void lin_stage2_kernel(const float* __restrict__ blin,
                                  float* __restrict__ outp) {
    int idx = blockIdx.x * blockDim.x + threadIdx.x;
    int m = idx >> 6;
    int n = idx & 63;
    float s = blin[n];
    #pragma unroll
    for (int ks = 0; ks < 8; ++ks) s += g_part[ks * (BSZ * IDIM) + idx];
    outp[(size_t)m * OUT_STRIDE + n] = s;
    g_fb[idx] = __float2half(s);
}

// ---------------- host launch ----------------
extern "C" void kernel_launch(void* const* d_in, const int* in_sizes, int n_in,
                              void* d_out, int out_size) {
    const float* x     = (const float*)d_in[0];
    const float* W_ih1 = (const float*)d_in[1];
    const float* W_hh1 = (const float*)d_in[2];
    const float* b_ih1 = (const float*)d_in[3];
    const float* b_hh1 = (const float*)d_in[4];
    const float* W_ih2 = (const float*)d_in[5];
    const float* W_hh2 = (const float*)d_in[6];
    const float* b_ih2 = (const float*)d_in[7];
    const float* b_hh2 = (const float*)d_in[8];
    const float* W_lin = (const float*)d_in[9];
    const float* b_lin = (const float*)d_in[10];
    float* out = (float*)d_out;

    void *wih1, *whh1, *wih2, *whh2, *wlinp, *xh, *h1, *h2, *h2hist, *c1, *c2, *fb;
    void *bias1, *bias2, *blinp;
    cudaGetSymbolAddress(&wih1, g_wih1);   cudaGetSymbolAddress(&whh1, g_whh1);
    cudaGetSymbolAddress(&wih2, g_wih2);   cudaGetSymbolAddress(&whh2, g_whh2);
    cudaGetSymbolAddress(&wlinp, g_wlinp);
    cudaGetSymbolAddress(&xh, g_x);
    cudaGetSymbolAddress(&h1, g_h1);       cudaGetSymbolAddress(&h2, g_h2);
    cudaGetSymbolAddress(&h2hist, g_h2hist);
    cudaGetSymbolAddress(&c1, g_c1);       cudaGetSymbolAddress(&c2, g_c2);
    cudaGetSymbolAddress(&fb, g_fb);
    cudaGetSymbolAddress(&bias1, g_bias1); cudaGetSymbolAddress(&bias2, g_bias2);
    cudaGetSymbolAddress(&blinp, g_blinp);

    f16* H1[2] = { (f16*)h1, (f16*)h1 + BSZ * HDIM };
    f16* H2[2] = { (f16*)h2, (f16*)h2 + BSZ * HDIM };
    f16* HIST  = (f16*)h2hist;

    constexpr int SMEM_MAIN = 3 * STAGE + 512;    // 98816
    constexpr int SMEM_HEAD = 3 * HSTAGE + 512;   // 74240
    cudaFuncSetAttribute(gemm_lstm, cudaFuncAttributeMaxDynamicSharedMemorySize, SMEM_MAIN);
    cudaFuncSetAttribute(gemm_head, cudaFuncAttributeMaxDynamicSharedMemorySize, SMEM_HEAD);

    // ---- prepasses (3 launches) ----
    prepW<<<(3 * QW1 + QIH1 + QLIN) / 256, 256>>>(W_hh1, W_ih2, W_hh2, W_ih1, W_lin);
    prepX<<<(BSZ * TSEQ * IDIM / 4) / 256, 256>>>(x);
    prepMisc<<<(BSZ * HDIM) / 256, 256>>>(b_ih1, b_hh1, b_ih2, b_hh2, b_lin);

    const dim3 gL(G4H / 128, BSZ / 128);   // (32, 8)

    for (int s = 0; s < NSTEP; ++s) {
        int rp = s & 1, wp = rp ^ 1;

        const f16* a1; int s1;
        if (s < TSEQ) { a1 = (const f16*)xh + (size_t)s * IDIM; s1 = TSEQ * IDIM; }
        else          { a1 = (const f16*)fb; s1 = IDIM; }

        // layer 1
        gemm_lstm<<<gL, 256, SMEM_MAIN>>>(
            a1, s1, 1,
            H1[rp], HDIM, 16,
            (const f16*)wih1, IDIM,
            (const f16*)whh1, HDIM,
            (const float*)bias1,
            (float*)c1, H1[wp], nullptr);

        // layer 2: shadow history for steps 0..62 and 79 (slot 63)
        f16* hp = nullptr;
        if (s < NBATCH)           hp = HIST + (size_t)s * BSZ * HDIM;
        else if (s == NSTEP - 1)  hp = HIST + (size_t)63 * BSZ * HDIM;
        gemm_lstm<<<gL, 256, SMEM_MAIN>>>(
            H1[wp], HDIM, 16,
            H2[rp], HDIM, 16,
            (const f16*)wih2, HDIM,
            (const f16*)whh2, HDIM,
            (const float*)bias2,
            (float*)c2, H2[wp], hp);

        // inline head only where feedback is consumed (s = 63..78)
        if (s >= TSEQ - 1 && s < NSTEP - 1) {
            lin_stage1_kernel<<<dim3(BSZ / 64, 8), 256>>>(H2[wp], W_lin);
            lin_stage2_kernel<<<(BSZ * IDIM) / 256, 256>>>(b_lin, out + (size_t)s * IDIM);
        }
    }

    // batched head: steps 0..62 + 79, M = 64*1024 rows, N = 64
    gemm_head<<<dim3(1, HSLOTS * 8), 256, SMEM_HEAD>>>(
        HIST, (const f16*)wlinp, (const float*)blinp, out);
}

// round 15
// speedup vs baseline: 1.1505x; 1.1505x over previous
#include <cuda_runtime.h>
#include <cuda_fp16.h>
#include <cstdint>
#include <math.h>

#define BSZ   1024
#define TSEQ  64
#define IDIM  64
#define HDIM  1024
#define FUT   16
#define NSTEP (TSEQ + FUT)          // 80
#define G4H   (4 * HDIM)            // 4096
#define OUT_STRIDE (NSTEP * IDIM)   // 5120
#define NBATCH 63                   // deferred-head steps 0..62
#define HSLOTS 64                   // + slot 63 = step 79

typedef __half f16;

// ---------------- device scratch (static; no runtime allocation) ----------------
__device__ f16 g_wih1[G4H * IDIM];
__device__ f16 g_whh1[G4H * HDIM];
__device__ f16 g_wih2[G4H * HDIM];
__device__ f16 g_whh2[G4H * HDIM];
__device__ f16 g_wlinp[128 * HDIM];           // W_lin padded to 128 rows
__device__ float g_bias1[G4H], g_bias2[G4H];
__device__ float g_blinp[128];
__device__ f16 g_x[BSZ * TSEQ * IDIM];
__device__ f16 g_h1[2][BSZ * HDIM];
__device__ f16 g_h2[2][BSZ * HDIM];
__device__ f16 g_h2hist[(size_t)HSLOTS * BSZ * HDIM]; // slots 0..62 = steps 0..62, 63 = step 79
__device__ float g_c1[BSZ * HDIM], g_c2[BSZ * HDIM];
__device__ f16 g_fb[BSZ * IDIM];
__device__ float g_part[8 * BSZ * IDIM];

// ---------------- helpers ----------------
__device__ __forceinline__ uint32_t smem_u32(const void* p) {
    return (uint32_t)__cvta_generic_to_shared(p);
}
__device__ __forceinline__ void cp16(uint32_t dst, const void* src) {
    asm volatile("cp.async.cg.shared.global [%0], [%1], 16;\n" :: "r"(dst), "l"(src));
}
__device__ __forceinline__ void cp_commit() { asm volatile("cp.async.commit_group;\n"); }
template<int N> __device__ __forceinline__ void cp_wait() {
    asm volatile("cp.async.wait_group %0;\n" :: "n"(N));
}
__device__ __forceinline__ void ldsm4(uint32_t* r, uint32_t a) {
    asm volatile("ldmatrix.sync.aligned.m8n8.x4.shared.b16 {%0,%1,%2,%3}, [%4];"
        : "=r"(r[0]), "=r"(r[1]), "=r"(r[2]), "=r"(r[3]) : "r"(a));
}
__device__ __forceinline__ void mma16816(float* d, const uint32_t* a, uint32_t b0, uint32_t b1) {
    asm volatile("mma.sync.aligned.m16n8k16.row.col.f32.f16.f16.f32 "
        "{%0,%1,%2,%3}, {%4,%5,%6,%7}, {%8,%9}, {%0,%1,%2,%3};"
        : "+f"(d[0]), "+f"(d[1]), "+f"(d[2]), "+f"(d[3])
        : "r"(a[0]), "r"(a[1]), "r"(a[2]), "r"(a[3]), "r"(b0), "r"(b1));
}
#define SWZ(x) ((x) ^ (((x) >> 3) & 0x70))

__device__ __forceinline__ float sigm(float x) { return 1.f / (1.f + __expf(-x)); }
__device__ __forceinline__ float tanh_f(float x) { return 2.f / (1.f + __expf(-2.f * x)) - 1.f; }

// ---------------- prepass kernels (3 launches total) ----------------
#define QW1 (G4H * HDIM / 4)
#define QIH1 (G4H * IDIM / 4)
#define QLIN (128 * HDIM / 4)
__global__ void prepW(const float* __restrict__ whh1, const float* __restrict__ wih2,
                      const float* __restrict__ whh2, const float* __restrict__ wih1,
                      const float* __restrict__ wlin) {
    int q = blockIdx.x * blockDim.x + threadIdx.x;
    if (q < 3 * QW1) {
        const float* src = (q < QW1) ? whh1 : ((q < 2 * QW1) ? wih2 : whh2);
        f16* dst = (q < QW1) ? g_whh1 : ((q < 2 * QW1) ? g_wih2 : g_whh2);
        int e = (q % QW1) * 4;
        int n = e >> 10, k = e & 1023;
        int pn = ((n & 1023) << 2) | (n >> 10);
        float4 v = *(const float4*)(src + e);
        dst[(size_t)pn * 1024 + k + 0] = __float2half(v.x);
        dst[(size_t)pn * 1024 + k + 1] = __float2half(v.y);
        dst[(size_t)pn * 1024 + k + 2] = __float2half(v.z);
        dst[(size_t)pn * 1024 + k + 3] = __float2half(v.w);
    } else if (q < 3 * QW1 + QIH1) {
        int e = (q - 3 * QW1) * 4;
        int n = e >> 6, k = e & 63;
        int pn = ((n & 1023) << 2) | (n >> 10);
        float4 v = *(const float4*)(wih1 + e);
        g_wih1[(size_t)pn * 64 + k + 0] = __float2half(v.x);
        g_wih1[(size_t)pn * 64 + k + 1] = __float2half(v.y);
        g_wih1[(size_t)pn * 64 + k + 2] = __float2half(v.z);
        g_wih1[(size_t)pn * 64 + k + 3] = __float2half(v.w);
    } else {
        int e = (q - 3 * QW1 - QIH1) * 4;
        int row = e >> 10;
        if (row < 64) {
            float4 v = *(const float4*)(wlin + e);
            g_wlinp[e + 0] = __float2half(v.x);
            g_wlinp[e + 1] = __float2half(v.y);
            g_wlinp[e + 2] = __float2half(v.z);
            g_wlinp[e + 3] = __float2half(v.w);
        } else {
            f16 z = __float2half(0.f);
            g_wlinp[e + 0] = z; g_wlinp[e + 1] = z; g_wlinp[e + 2] = z; g_wlinp[e + 3] = z;
        }
    }
}
__global__ void prepX(const float* __restrict__ x) {
    size_t e = ((size_t)blockIdx.x * blockDim.x + threadIdx.x) * 4;
    float4 v = *(const float4*)(x + e);
    g_x[e + 0] = __float2half(v.x);
    g_x[e + 1] = __float2half(v.y);
    g_x[e + 2] = __float2half(v.z);
    g_x[e + 3] = __float2half(v.w);
}
__global__ void prepMisc(const float* b1a, const float* b1b,
                         const float* b2a, const float* b2b, const float* blin) {
    int i = blockIdx.x * blockDim.x + threadIdx.x;
    f16 z = __float2half(0.f);
    g_h1[0][i] = z; g_h2[0][i] = z;
    g_c1[i] = 0.f;  g_c2[i] = 0.f;
    if (i < BSZ * IDIM) g_fb[i] = z;
    if (i < G4H) {
        int pn = ((i & 1023) << 2) | (i >> 10);
        g_bias1[pn] = b1a[i] + b1b[i];
        g_bias2[pn] = b2a[i] + b2b[i];
    }
    if (i < 128) g_blinp[i] = (i < 64) ? blin[i] : 0.f;
}

// ---------------- GEMM body (device function; fp16 mma.sync, fused LSTM epilogue) ----------------
// C tile 128(M) x 128(N). Two A phases: nA chunks of (A1,W1), nB of (A2,W2).
// K-chunk = 64 fp16 (128B rows, SW128 swizzle). Single-barrier 3-stage pipeline.
#define STAGE 32768   // A 16K | W 16K

__device__ __forceinline__ void gemm_body(char* smem,
    const f16* __restrict__ A1, int s1, int nA,
    const f16* __restrict__ A2, int nB,
    const f16* __restrict__ W1, int w1s,
    const f16* __restrict__ W2,
    const float* __restrict__ bias,
    float* __restrict__ cbuf, f16* __restrict__ H, f16* __restrict__ hist,
    int mBase, int nBase)
{
    const int tid = threadIdx.x;
    const uint32_t sb = smem_u32(smem);

    float* sbias = (float*)(smem + 3 * STAGE);
    if (tid < 128) sbias[tid] = bias[nBase + tid];

    const int C = nA + nB;

    auto load_chunk = [&](int c, int st) {
        const f16 *A, *W; int as, ws;
        if (c < nA) { A = A1 + c * 64; as = s1; W = W1 + c * 64; ws = w1s; }
        else        { int d = c - nA;
                      A = A2 + d * 64; as = HDIM; W = W2 + d * 64; ws = HDIM; }
        uint32_t base = sb + st * STAGE;
        #pragma unroll
        for (int j = 0; j < 4; ++j) {
            int o = tid + j * 256; int row = o >> 3; int eo = (o & 7) * 8;
            uint32_t boff = SWZ(row * 128 + eo * 2);
            cp16(base + boff,         A + (size_t)(mBase + row) * as + eo);
            cp16(base + 16384 + boff, W + (size_t)(nBase + row) * ws + eo);
        }
        cp_commit();
    };

    const int w = tid >> 5, l = tid & 31;
    const int wm = (w & 3) * 32, wn = (w >> 2) * 64;

    float acc[2][8][4];
    #pragma unroll
    for (int mt = 0; mt < 2; ++mt)
        #pragma unroll
        for (int nt = 0; nt < 8; ++nt)
            #pragma unroll
            for (int j = 0; j < 4; ++j) acc[mt][nt][j] = 0.f;

    load_chunk(0, 0);
    if (C > 1) load_chunk(1, 1); else cp_commit();

    // swizzled base addresses; low 7 bits hold only bit 4, so SWZ(b + ks*32) == SWZ(b) ^ (ks*32)
    uint32_t aB[2], wB[4];
    {
        const int aColSub = (l >> 4) << 4;
        #pragma unroll
        for (int mt = 0; mt < 2; ++mt)
            aB[mt] = SWZ((uint32_t)(((wm + mt * 16 + (l & 15)) << 7) + aColSub));
        const int wColSub = ((l >> 3) & 1) << 4;
        #pragma unroll
        for (int ng = 0; ng < 4; ++ng)
            wB[ng] = SWZ((uint32_t)(((wn + ng * 16 + (l & 7) + (((l >> 4) & 1) << 3)) << 7) + wColSub));
    }

    for (int c = 0; c < C; ++c) {
        const int st = c % 3;
        cp_wait<1>();
        __syncthreads();

        if (c + 2 < C) load_chunk(c + 2, (c + 2) % 3);
        else cp_commit();

        const uint32_t bA = sb + st * STAGE;
        const uint32_t bW = bA + 16384;

        #pragma unroll
        for (int ks = 0; ks < 4; ++ks) {
            const uint32_t kx = (uint32_t)(ks << 5);
            uint32_t af[2][4], wf[4][4];
            #pragma unroll
            for (int mt = 0; mt < 2; ++mt) ldsm4(af[mt], bA + (aB[mt] ^ kx));
            #pragma unroll
            for (int ng = 0; ng < 4; ++ng) ldsm4(wf[ng], bW + (wB[ng] ^ kx));
            #pragma unroll
            for (int mt = 0; mt < 2; ++mt) {
                #pragma unroll
                for (int ng = 0; ng < 4; ++ng) {
                    mma16816(acc[mt][ng * 2],     af[mt], wf[ng][0], wf[ng][1]);
                    mma16816(acc[mt][ng * 2 + 1], af[mt], wf[ng][2], wf[ng][3]);
                }
            }
        }
    }

    // ---------------- fused LSTM epilogue ----------------
    const int gr = l >> 2;
    const bool odd = l & 1;
    const int q = (l >> 1) & 1;

    #pragma unroll
    for (int mt = 0; mt < 2; ++mt) {
        #pragma unroll
        for (int nt = 0; nt < 8; ++nt) {
            float c0 = acc[mt][nt][0], c1 = acc[mt][nt][1];
            float c2 = acc[mt][nt][2], c3 = acc[mt][nt][3];
            float sx = odd ? c0 : c2;
            float sy = odd ? c1 : c3;
            float rx = __shfl_xor_sync(0xFFFFFFFFu, sx, 1);
            float ry = __shfl_xor_sync(0xFFFFFFFFu, sy, 1);
            float iv, fv, gv, ov;
            if (!odd) { iv = c0; fv = c1; gv = rx; ov = ry; }
            else      { iv = rx; fv = ry; gv = c2; ov = c3; }
            int nn  = wn + nt * 8 + q * 4;
            int row = mBase + wm + mt * 16 + gr + (odd ? 8 : 0);
            float xi = iv + sbias[nn + 0];
            float xf = fv + sbias[nn + 1];
            float xg = gv + sbias[nn + 2];
            float xo = ov + sbias[nn + 3];
            float gi = sigm(xi), gf = sigm(xf), gg = tanh_f(xg), go = sigm(xo);
            int unit = (nBase + nn) >> 2;
            size_t idx = (size_t)row * HDIM + unit;
            float cn = gf * cbuf[idx] + gi * gg;
            cbuf[idx] = cn;
            float hn = go * tanh_f(cn);
            f16 hv = __float2half(hn);
            H[idx] = hv;
            if (hist) hist[idx] = hv;
        }
    }
}

// single-layer wrapper
__global__ void __launch_bounds__(256, 2)
gemm_lstm(const f16* __restrict__ A1, int s1, int nA,
          const f16* __restrict__ A2, int nB,
          const f16* __restrict__ W1, int w1s,
          const f16* __restrict__ W2,
          const float* __restrict__ bias,
          float* __restrict__ cbuf, f16* __restrict__ H,
          f16* __restrict__ hist)
{
    extern __shared__ __align__(1024) char smem[];
    gemm_body(smem, A1, s1, nA, A2, nB, W1, w1s, W2, bias, cbuf, H, hist,
              blockIdx.y * 128, blockIdx.x * 128);
}

// merged kernel: M(s) = { L2(s-1)  [blockIdx.y < 8],  L1(s)  [blockIdx.y >= 8] }
// Intra-launch independent: L2(s-1) reads h1(s-1), h2(s-2); L1(s) reads x(s), h1(s-1),
// writes the OTHER h1 buffer. L2 CTAs are scheduled first (long, 32 chunks); L1 (17) fill tail.
__global__ void __launch_bounds__(256, 2)
gemm_merged(const f16* __restrict__ h1rd,     // H1[s&1] (read by both parts)
            const f16* __restrict__ h2rd,     // H2[(s&1)^1]
            f16* __restrict__ h2wr,           // H2[s&1]
            f16* __restrict__ hist,           // slot s-1
            const f16* __restrict__ xs,       // x(s)
            f16* __restrict__ h1wr)           // H1[(s&1)^1]
{
    extern __shared__ __align__(1024) char smem[];
    const int nBase = blockIdx.x * 128;
    if (blockIdx.y < 8) {
        gemm_body(smem, h1rd, HDIM, 16, h2rd, 16, g_wih2, HDIM, g_whh2,
                  g_bias2, g_c2, h2wr, hist, blockIdx.y * 128, nBase);
    } else {
        gemm_body(smem, xs, TSEQ * IDIM, 1, h1rd, 16, g_wih1, IDIM, g_whh1,
                  g_bias1, g_c1, h1wr, nullptr, (blockIdx.y - 8) * 128, nBase);
    }
}

// ---------------- batched head kernel: tile 128(M) x 64(N) ----------------
#define HSTAGE 24576   // A 16K | W 8K

__global__ void __launch_bounds__(256, 2)
gemm_head(const f16* __restrict__ A, const f16* __restrict__ Wl,
          const float* __restrict__ bias, float* __restrict__ outp)
{
    extern __shared__ __align__(1024) char smem[];
    const int tid = threadIdx.x;
    const size_t mBase = (size_t)blockIdx.y * 128;
    const uint32_t sb = smem_u32(smem);

    float* sbias = (float*)(smem + 3 * HSTAGE);
    if (tid < 64) sbias[tid] = bias[tid];

    auto load_chunk = [&](int c, int st) {
        uint32_t base = sb + st * HSTAGE;
        const f16* Ap = A + c * 64;
        const f16* Wp = Wl + c * 64;
        #pragma unroll
        for (int j = 0; j < 4; ++j) {
            int o = tid + j * 256; int row = o >> 3; int eo = (o & 7) * 8;
            uint32_t boff = SWZ(row * 128 + eo * 2);
            cp16(base + boff, Ap + (mBase + row) * (size_t)HDIM + eo);
        }
        #pragma unroll
        for (int j = 0; j < 2; ++j) {
            int o = tid + j * 256; int row = o >> 3; int eo = (o & 7) * 8;
            uint32_t boff = SWZ(row * 128 + eo * 2);
            cp16(base + 16384 + boff, Wp + (size_t)row * HDIM + eo);
        }
        cp_commit();
    };

    const int w = tid >> 5, l = tid & 31;
    const int wm = (w & 3) * 32, wn = (w >> 2) * 32;

    float acc[2][4][4];
    #pragma unroll
    for (int mt = 0; mt < 2; ++mt)
        #pragma unroll
        for (int nt = 0; nt < 4; ++nt)
            #pragma unroll
            for (int j = 0; j < 4; ++j) acc[mt][nt][j] = 0.f;

    load_chunk(0, 0);
    load_chunk(1, 1);

    uint32_t aB[2], wB[2];
    {
        const int aColSub = (l >> 4) << 4;
        #pragma unroll
        for (int mt = 0; mt < 2; ++mt)
            aB[mt] = SWZ((uint32_t)(((wm + mt * 16 + (l & 15)) << 7) + aColSub));
        const int wColSub = ((l >> 3) & 1) << 4;
        #pragma unroll
        for (int ng = 0; ng < 2; ++ng)
            wB[ng] = SWZ((uint32_t)(((wn + ng * 16 + (l & 7) + (((l >> 4) & 1) << 3)) << 7) + wColSub));
    }

    const int C = 16;
    for (int c = 0; c < C; ++c) {
        const int st = c % 3;
        cp_wait<1>();
        __syncthreads();

        if (c + 2 < C) load_chunk(c + 2, (c + 2) % 3);
        else cp_commit();

        const uint32_t bA = sb + st * HSTAGE;
        const uint32_t bW = bA + 16384;

        #pragma unroll
        for (int ks = 0; ks < 4; ++ks) {
            const uint32_t kx = (uint32_t)(ks << 5);
            uint32_t af[2][4], wf[2][4];
            #pragma unroll
            for (int mt = 0; mt < 2; ++mt) ldsm4(af[mt], bA + (aB[mt] ^ kx));
            #pragma unroll
            for (int ng = 0; ng < 2; ++ng) ldsm4(wf[ng], bW + (wB[ng] ^ kx));
            #pragma unroll
            for (int mt = 0; mt < 2; ++mt) {
                #pragma unroll
                for (int ng = 0; ng < 2; ++ng) {
                    mma16816(acc[mt][ng * 2],     af[mt], wf[ng][0], wf[ng][1]);
                    mma16816(acc[mt][ng * 2 + 1], af[mt], wf[ng][2], wf[ng][3]);
                }
            }
        }
    }

    #pragma unroll
    for (int mt = 0; mt < 2; ++mt) {
        #pragma unroll
        for (int nt = 0; nt < 4; ++nt) {
            int col = wn + nt * 8 + 2 * (l & 3);
            size_t r0 = mBase + wm + mt * 16 + (l >> 2);
            size_t r1 = r0 + 8;
            int stp = (int)(r0 >> 10);
            if (stp == 63) stp = 79;
            float v0 = acc[mt][nt][0] + sbias[col];
            float v1 = acc[mt][nt][1] + sbias[col + 1];
            float v2 = acc[mt][nt][2] + sbias[col];
            float v3 = acc[mt][nt][3] + sbias[col + 1];
            float* p0 = outp + (r0 & 1023) * OUT_STRIDE + (size_t)stp * IDIM + col;
            float* p1 = outp + (r1 & 1023) * OUT_STRIDE + (size_t)stp * IDIM + col;
            p0[0] = v0; p0[1] = v1;
            p1[0] = v2; p1[1] = v3;
        }
    }
}

// ---------------- inline head (steps 63..78): fp32 split-K ----------------
__global__ __launch_bounds__(256)
void lin_stage1_kernel(const f16* __restrict__ H, const float* __restrict__ Wlin) {
    __shared__ float Hs[16][68];
    __shared__ float Ws[16][68];

    const int tid = threadIdx.x;
    const int mBase = blockIdx.x * 64;
    const int ks = blockIdx.y;
    const int kBeg = ks * 128;

    const int lr = tid >> 2;
    const int lc = (tid & 3) << 2;
    const int tx = tid & 15;
    const int ty = tid >> 4;

    float acc[4][4];
    #pragma unroll
    for (int i = 0; i < 4; ++i)
        #pragma unroll
        for (int j = 0; j < 4; ++j) acc[i][j] = 0.f;

    for (int k0 = kBeg; k0 < kBeg + 128; k0 += 16) {
        size_t hoff = (size_t)(mBase + lr) * HDIM + k0 + lc;
        const __half2* ph = (const __half2*)(H + hoff);
        float2 h0 = __half22float2(ph[0]);
        float2 h1 = __half22float2(ph[1]);
        Hs[lc + 0][lr] = h0.x; Hs[lc + 1][lr] = h0.y;
        Hs[lc + 2][lr] = h1.x; Hs[lc + 3][lr] = h1.y;
        float4 wv = *reinterpret_cast<const float4*>(&Wlin[(size_t)lr * HDIM + k0 + lc]);
        Ws[lc + 0][lr] = wv.x; Ws[lc + 1][lr] = wv.y;
        Ws[lc + 2][lr] = wv.z; Ws[lc + 3][lr] = wv.w;
        __syncthreads();

        #pragma unroll
        for (int kk = 0; kk < 16; ++kk) {
            float a[4], wv2[4];
            #pragma unroll
            for (int i = 0; i < 4; ++i) a[i] = Hs[kk][ty * 4 + i];
            #pragma unroll
            for (int j = 0; j < 4; ++j) wv2[j] = Ws[kk][tx * 4 + j];
            #pragma unroll
            for (int i = 0; i < 4; ++i)
                #pragma unroll
                for (int j = 0; j < 4; ++j)
                    acc[i][j] = fmaf(a[i], wv2[j], acc[i][j]);
        }
        __syncthreads();
    }

    #pragma unroll
    for (int i = 0; i < 4; ++i) {
        int m = mBase + ty * 4 + i;
        #pragma unroll
        for (int j = 0; j < 4; ++j) {
            int n = tx * 4 + j;
            g_part[(size_t)ks * (BSZ * IDIM) + m * IDIM + n] = acc[i][j];
        }
    }
}

__global__ void lin_stage2_kernel(const float* __restrict__ blin,
                                  float* __restrict__ outp) {
    int idx = blockIdx.x * blockDim.x + threadIdx.x;
    int m = idx >> 6;
    int n = idx & 63;
    float s = blin[n];
    #pragma unroll
    for (int ks = 0; ks < 8; ++ks) s += g_part[ks * (BSZ * IDIM) + idx];
    outp[(size_t)m * OUT_STRIDE + n] = s;
    g_fb[idx] = __float2half(s);
}

// ---------------- host launch ----------------
extern "C" void kernel_launch(void* const* d_in, const int* in_sizes, int n_in,
                              void* d_out, int out_size) {
    const float* x     = (const float*)d_in[0];
    const float* W_ih1 = (const float*)d_in[1];
    const float* W_hh1 = (const float*)d_in[2];
    const float* b_ih1 = (const float*)d_in[3];
    const float* b_hh1 = (const float*)d_in[4];
    const float* W_ih2 = (const float*)d_in[5];
    const float* W_hh2 = (const float*)d_in[6];
    const float* b_ih2 = (const float*)d_in[7];
    const float* b_hh2 = (const float*)d_in[8];
    const float* W_lin = (const float*)d_in[9];
    const float* b_lin = (const float*)d_in[10];
    float* out = (float*)d_out;

    void *wih1, *whh1, *wih2, *whh2, *wlinp, *xh, *h1, *h2, *h2hist, *c1, *c2, *fb;
    void *bias1, *bias2, *blinp;
    cudaGetSymbolAddress(&wih1, g_wih1);   cudaGetSymbolAddress(&whh1, g_whh1);
    cudaGetSymbolAddress(&wih2, g_wih2);   cudaGetSymbolAddress(&whh2, g_whh2);
    cudaGetSymbolAddress(&wlinp, g_wlinp);
    cudaGetSymbolAddress(&xh, g_x);
    cudaGetSymbolAddress(&h1, g_h1);       cudaGetSymbolAddress(&h2, g_h2);
    cudaGetSymbolAddress(&h2hist, g_h2hist);
    cudaGetSymbolAddress(&c1, g_c1);       cudaGetSymbolAddress(&c2, g_c2);
    cudaGetSymbolAddress(&fb, g_fb);
    cudaGetSymbolAddress(&bias1, g_bias1); cudaGetSymbolAddress(&bias2, g_bias2);
    cudaGetSymbolAddress(&blinp, g_blinp);

    f16* H1[2] = { (f16*)h1, (f16*)h1 + BSZ * HDIM };
    f16* H2[2] = { (f16*)h2, (f16*)h2 + BSZ * HDIM };
    f16* HIST  = (f16*)h2hist;

    constexpr int SMEM_MAIN = 3 * STAGE + 512;    // 98816
    constexpr int SMEM_HEAD = 3 * HSTAGE + 512;   // 74240
    cudaFuncSetAttribute(gemm_lstm,   cudaFuncAttributeMaxDynamicSharedMemorySize, SMEM_MAIN);
    cudaFuncSetAttribute(gemm_merged, cudaFuncAttributeMaxDynamicSharedMemorySize, SMEM_MAIN);
    cudaFuncSetAttribute(gemm_head,   cudaFuncAttributeMaxDynamicSharedMemorySize, SMEM_HEAD);

    // ---- prepasses (3 launches) ----
    prepW<<<(3 * QW1 + QIH1 + QLIN) / 256, 256>>>(W_hh1, W_ih2, W_hh2, W_ih1, W_lin);
    prepX<<<(BSZ * TSEQ * IDIM / 4) / 256, 256>>>(x);
    prepMisc<<<(BSZ * HDIM) / 256, 256>>>(b_ih1, b_hh1, b_ih2, b_hh2, b_lin);

    const dim3 gL(G4H / 128, BSZ / 128);   // (32, 8)
    const dim3 gM(G4H / 128, 16);          // (32, 16) merged

    // M(0) = L1(0): reads H1[0] (zeros), writes H1[1]
    gemm_lstm<<<gL, 256, SMEM_MAIN>>>(
        (const f16*)xh, TSEQ * IDIM, 1,
        H1[0], 16,
        (const f16*)wih1, IDIM, (const f16*)whh1,
        (const float*)bias1, (float*)c1, H1[1], nullptr);

    // encoding phase merged: M(s) = { L2(s-1), L1(s) }, s = 1..63
    for (int s = 1; s <= 63; ++s) {
        int p = s & 1;
        gemm_merged<<<gM, 256, SMEM_MAIN>>>(
            H1[p],                // h1(s-1): read by both parts
            H2[p ^ 1],            // h2(s-2)
            H2[p],                // h2(s-1) out
            HIST + (size_t)(s - 1) * BSZ * HDIM,   // slots 0..62
            (const f16*)xh + (size_t)s * IDIM,
            H1[p ^ 1]);           // h1(s) out
    }

    // L2(63): reads H1[0] (h1(63)), H2[1] (h2(62)), writes H2[0]; no hist (inline head covers 63)
    gemm_lstm<<<gL, 256, SMEM_MAIN>>>(
        H1[0], HDIM, 16,
        H2[1], 16,
        (const f16*)wih2, HDIM, (const f16*)whh2,
        (const float*)bias2, (float*)c2, H2[0], nullptr);

    // inline head for step 63 (produces out(63) + fb for L1(64))
    lin_stage1_kernel<<<dim3(BSZ / 64, 8), 256>>>(H2[0], W_lin);
    lin_stage2_kernel<<<(BSZ * IDIM) / 256, 256>>>(b_lin, out + (size_t)63 * IDIM);

    // future phase: serial (fb dependency)
    for (int s = 64; s < NSTEP; ++s) {
        int rp = s & 1, wp = rp ^ 1;

        gemm_lstm<<<gL, 256, SMEM_MAIN>>>(
            (const f16*)fb, IDIM, 1,
            H1[rp], 16,
            (const f16*)wih1, IDIM, (const f16*)whh1,
            (const float*)bias1, (float*)c1, H1[wp], nullptr);

        f16* hp = (s == NSTEP - 1) ? HIST + (size_t)63 * BSZ * HDIM : nullptr;
        gemm_lstm<<<gL, 256, SMEM_MAIN>>>(
            H1[wp], HDIM, 16,
            H2[rp], 16,
            (const f16*)wih2, HDIM, (const f16*)whh2,
            (const float*)bias2, (float*)c2, H2[wp], hp);

        if (s < NSTEP - 1) {
            lin_stage1_kernel<<<dim3(BSZ / 64, 8), 256>>>(H2[wp], W_lin);
            lin_stage2_kernel<<<(BSZ * IDIM) / 256, 256>>>(b_lin, out + (size_t)s * IDIM);
        }
    }

    // batched head: steps 0..62 + 79
    gemm_head<<<dim3(1, HSLOTS * 8), 256, SMEM_HEAD>>>(
        HIST, (const f16*)wlinp, (const float*)blinp, out);
}

// round 16
// speedup vs baseline: 1.1863x; 1.0312x over previous
#include <cuda_runtime.h>
#include <cuda_fp16.h>
#include <cstdint>
#include <math.h>

#define BSZ   1024
#define TSEQ  64
#define IDIM  64
#define HDIM  1024
#define FUT   16
#define NSTEP (TSEQ + FUT)          // 80
#define G4H   (4 * HDIM)            // 4096
#define OUT_STRIDE (NSTEP * IDIM)   // 5120
#define NBATCH 63                   // deferred-head steps 0..62
#define HSLOTS 64                   // + slot 63 = step 79

typedef __half f16;

// ---------------- device scratch (static; no runtime allocation) ----------------
__device__ f16 g_wih1[G4H * IDIM];
__device__ f16 g_whh1[G4H * HDIM];
__device__ f16 g_wih2[G4H * HDIM];
__device__ f16 g_whh2[G4H * HDIM];
__device__ f16 g_wlinp[128 * HDIM];           // W_lin padded to 128 rows
__device__ float g_bias1[G4H], g_bias2[G4H];
__device__ float g_blinp[128];
__device__ f16 g_x[BSZ * TSEQ * IDIM];
__device__ f16 g_h1[2][BSZ * HDIM];
__device__ f16 g_h2[2][BSZ * HDIM];
__device__ f16 g_h2hist[(size_t)HSLOTS * BSZ * HDIM]; // slots 0..62 = steps 0..62, 63 = step 79
__device__ float g_c1[BSZ * HDIM], g_c2[BSZ * HDIM];
__device__ f16 g_fb[BSZ * IDIM];
__device__ float g_part[8 * BSZ * IDIM];
__device__ float g_gates[BSZ * G4H];          // future-phase L1a partial gate preacts (16 MB)

// ---------------- helpers ----------------
__device__ __forceinline__ uint32_t smem_u32(const void* p) {
    return (uint32_t)__cvta_generic_to_shared(p);
}
__device__ __forceinline__ void cp16(uint32_t dst, const void* src) {
    asm volatile("cp.async.cg.shared.global [%0], [%1], 16;\n" :: "r"(dst), "l"(src));
}
__device__ __forceinline__ void cp_commit() { asm volatile("cp.async.commit_group;\n"); }
template<int N> __device__ __forceinline__ void cp_wait() {
    asm volatile("cp.async.wait_group %0;\n" :: "n"(N));
}
__device__ __forceinline__ void ldsm4(uint32_t* r, uint32_t a) {
    asm volatile("ldmatrix.sync.aligned.m8n8.x4.shared.b16 {%0,%1,%2,%3}, [%4];"
        : "=r"(r[0]), "=r"(r[1]), "=r"(r[2]), "=r"(r[3]) : "r"(a));
}
__device__ __forceinline__ void mma16816(float* d, const uint32_t* a, uint32_t b0, uint32_t b1) {
    asm volatile("mma.sync.aligned.m16n8k16.row.col.f32.f16.f16.f32 "
        "{%0,%1,%2,%3}, {%4,%5,%6,%7}, {%8,%9}, {%0,%1,%2,%3};"
        : "+f"(d[0]), "+f"(d[1]), "+f"(d[2]), "+f"(d[3])
        : "r"(a[0]), "r"(a[1]), "r"(a[2]), "r"(a[3]), "r"(b0), "r"(b1));
}
#define SWZ(x) ((x) ^ (((x) >> 3) & 0x70))

__device__ __forceinline__ float sigm(float x) { return 1.f / (1.f + __expf(-x)); }
__device__ __forceinline__ float tanh_f(float x) { return 2.f / (1.f + __expf(-2.f * x)) - 1.f; }

// ---------------- prepass kernels (3 launches total) ----------------
#define QW1 (G4H * HDIM / 4)
#define QIH1 (G4H * IDIM / 4)
#define QLIN (128 * HDIM / 4)
__global__ void prepW(const float* __restrict__ whh1, const float* __restrict__ wih2,
                      const float* __restrict__ whh2, const float* __restrict__ wih1,
                      const float* __restrict__ wlin) {
    int q = blockIdx.x * blockDim.x + threadIdx.x;
    if (q < 3 * QW1) {
        const float* src = (q < QW1) ? whh1 : ((q < 2 * QW1) ? wih2 : whh2);
        f16* dst = (q < QW1) ? g_whh1 : ((q < 2 * QW1) ? g_wih2 : g_whh2);
        int e = (q % QW1) * 4;
        int n = e >> 10, k = e & 1023;
        int pn = ((n & 1023) << 2) | (n >> 10);
        float4 v = *(const float4*)(src + e);
        dst[(size_t)pn * 1024 + k + 0] = __float2half(v.x);
        dst[(size_t)pn * 1024 + k + 1] = __float2half(v.y);
        dst[(size_t)pn * 1024 + k + 2] = __float2half(v.z);
        dst[(size_t)pn * 1024 + k + 3] = __float2half(v.w);
    } else if (q < 3 * QW1 + QIH1) {
        int e = (q - 3 * QW1) * 4;
        int n = e >> 6, k = e & 63;
        int pn = ((n & 1023) << 2) | (n >> 10);
        float4 v = *(const float4*)(wih1 + e);
        g_wih1[(size_t)pn * 64 + k + 0] = __float2half(v.x);
        g_wih1[(size_t)pn * 64 + k + 1] = __float2half(v.y);
        g_wih1[(size_t)pn * 64 + k + 2] = __float2half(v.z);
        g_wih1[(size_t)pn * 64 + k + 3] = __float2half(v.w);
    } else {
        int e = (q - 3 * QW1 - QIH1) * 4;
        int row = e >> 10;
        if (row < 64) {
            float4 v = *(const float4*)(wlin + e);
            g_wlinp[e + 0] = __float2half(v.x);
            g_wlinp[e + 1] = __float2half(v.y);
            g_wlinp[e + 2] = __float2half(v.z);
            g_wlinp[e + 3] = __float2half(v.w);
        } else {
            f16 z = __float2half(0.f);
            g_wlinp[e + 0] = z; g_wlinp[e + 1] = z; g_wlinp[e + 2] = z; g_wlinp[e + 3] = z;
        }
    }
}
__global__ void prepX(const float* __restrict__ x) {
    size_t e = ((size_t)blockIdx.x * blockDim.x + threadIdx.x) * 4;
    float4 v = *(const float4*)(x + e);
    g_x[e + 0] = __float2half(v.x);
    g_x[e + 1] = __float2half(v.y);
    g_x[e + 2] = __float2half(v.z);
    g_x[e + 3] = __float2half(v.w);
}
__global__ void prepMisc(const float* b1a, const float* b1b,
                         const float* b2a, const float* b2b, const float* blin) {
    int i = blockIdx.x * blockDim.x + threadIdx.x;
    f16 z = __float2half(0.f);
    g_h1[0][i] = z; g_h2[0][i] = z;
    g_c1[i] = 0.f;  g_c2[i] = 0.f;
    if (i < BSZ * IDIM) g_fb[i] = z;
    if (i < G4H) {
        int pn = ((i & 1023) << 2) | (i >> 10);
        g_bias1[pn] = b1a[i] + b1b[i];
        g_bias2[pn] = b2a[i] + b2b[i];
    }
    if (i < 128) g_blinp[i] = (i < 64) ? blin[i] : 0.f;
}

// ---------------- GEMM body (device function; fp16 mma.sync) ----------------
// C tile 128(M) x 128(N). Two A phases: nA chunks of (A1,W1), nB of (A2,W2).
// K-chunk = 64 fp16 (128B rows, SW128 swizzle). Single-barrier 3-stage pipeline.
// MODE 0: fused LSTM epilogue; aux (optional) = fp32 gate-partials added to preacts.
// MODE 1: raw gate-partials write epilogue (acc -> aux buffer; no bias/activation).
#define STAGE 32768   // A 16K | W 16K

template<int MODE>
__device__ __forceinline__ void gemm_body(char* smem,
    const f16* __restrict__ A1, int s1, int nA,
    const f16* __restrict__ A2, int nB,
    const f16* __restrict__ W1, int w1s,
    const f16* __restrict__ W2,
    const float* __restrict__ bias,
    const float* __restrict__ auxin, float* __restrict__ auxout,
    float* __restrict__ cbuf, f16* __restrict__ H, f16* __restrict__ hist,
    int mBase, int nBase)
{
    const int tid = threadIdx.x;
    const uint32_t sb = smem_u32(smem);

    float* sbias = (float*)(smem + 3 * STAGE);
    if (MODE == 0) { if (tid < 128) sbias[tid] = bias[nBase + tid]; }

    const int C = nA + nB;

    auto load_chunk = [&](int c, int st) {
        const f16 *A, *W; int as, ws;
        if (c < nA) { A = A1 + c * 64; as = s1; W = W1 + c * 64; ws = w1s; }
        else        { int d = c - nA;
                      A = A2 + d * 64; as = HDIM; W = W2 + d * 64; ws = HDIM; }
        uint32_t base = sb + st * STAGE;
        #pragma unroll
        for (int j = 0; j < 4; ++j) {
            int o = tid + j * 256; int row = o >> 3; int eo = (o & 7) * 8;
            uint32_t boff = SWZ(row * 128 + eo * 2);
            cp16(base + boff,         A + (size_t)(mBase + row) * as + eo);
            cp16(base + 16384 + boff, W + (size_t)(nBase + row) * ws + eo);
        }
        cp_commit();
    };

    const int w = tid >> 5, l = tid & 31;
    const int wm = (w & 3) * 32, wn = (w >> 2) * 64;

    float acc[2][8][4];
    #pragma unroll
    for (int mt = 0; mt < 2; ++mt)
        #pragma unroll
        for (int nt = 0; nt < 8; ++nt)
            #pragma unroll
            for (int j = 0; j < 4; ++j) acc[mt][nt][j] = 0.f;

    load_chunk(0, 0);
    if (C > 1) load_chunk(1, 1); else cp_commit();

    // swizzled base addresses; low 7 bits hold only bit 4, so SWZ(b + ks*32) == SWZ(b) ^ (ks*32)
    uint32_t aB[2], wB[4];
    {
        const int aColSub = (l >> 4) << 4;
        #pragma unroll
        for (int mt = 0; mt < 2; ++mt)
            aB[mt] = SWZ((uint32_t)(((wm + mt * 16 + (l & 15)) << 7) + aColSub));
        const int wColSub = ((l >> 3) & 1) << 4;
        #pragma unroll
        for (int ng = 0; ng < 4; ++ng)
            wB[ng] = SWZ((uint32_t)(((wn + ng * 16 + (l & 7) + (((l >> 4) & 1) << 3)) << 7) + wColSub));
    }

    for (int c = 0; c < C; ++c) {
        const int st = c % 3;
        cp_wait<1>();
        __syncthreads();

        if (c + 2 < C) load_chunk(c + 2, (c + 2) % 3);
        else cp_commit();

        const uint32_t bA = sb + st * STAGE;
        const uint32_t bW = bA + 16384;

        #pragma unroll
        for (int ks = 0; ks < 4; ++ks) {
            const uint32_t kx = (uint32_t)(ks << 5);
            uint32_t af[2][4], wf[4][4];
            #pragma unroll
            for (int mt = 0; mt < 2; ++mt) ldsm4(af[mt], bA + (aB[mt] ^ kx));
            #pragma unroll
            for (int ng = 0; ng < 4; ++ng) ldsm4(wf[ng], bW + (wB[ng] ^ kx));
            #pragma unroll
            for (int mt = 0; mt < 2; ++mt) {
                #pragma unroll
                for (int ng = 0; ng < 4; ++ng) {
                    mma16816(acc[mt][ng * 2],     af[mt], wf[ng][0], wf[ng][1]);
                    mma16816(acc[mt][ng * 2 + 1], af[mt], wf[ng][2], wf[ng][3]);
                }
            }
        }
    }

    if (MODE == 1) {
        // ---------------- raw gate-partials epilogue (native fragment layout) ----------------
        #pragma unroll
        for (int mt = 0; mt < 2; ++mt) {
            #pragma unroll
            for (int nt = 0; nt < 8; ++nt) {
                int col = nBase + wn + nt * 8 + 2 * (l & 3);
                int r0 = mBase + wm + mt * 16 + (l >> 2);
                float* p0 = auxout + (size_t)r0 * G4H + col;
                float* p1 = auxout + (size_t)(r0 + 8) * G4H + col;
                p0[0] = acc[mt][nt][0]; p0[1] = acc[mt][nt][1];
                p1[0] = acc[mt][nt][2]; p1[1] = acc[mt][nt][3];
            }
        }
        return;
    }

    // ---------------- fused LSTM epilogue ----------------
    const int gr = l >> 2;
    const bool odd = l & 1;
    const int q = (l >> 1) & 1;

    #pragma unroll
    for (int mt = 0; mt < 2; ++mt) {
        #pragma unroll
        for (int nt = 0; nt < 8; ++nt) {
            float c0 = acc[mt][nt][0], c1 = acc[mt][nt][1];
            float c2 = acc[mt][nt][2], c3 = acc[mt][nt][3];
            float sx = odd ? c0 : c2;
            float sy = odd ? c1 : c3;
            float rx = __shfl_xor_sync(0xFFFFFFFFu, sx, 1);
            float ry = __shfl_xor_sync(0xFFFFFFFFu, sy, 1);
            float iv, fv, gv, ov;
            if (!odd) { iv = c0; fv = c1; gv = rx; ov = ry; }
            else      { iv = rx; fv = ry; gv = c2; ov = c3; }
            int nn  = wn + nt * 8 + q * 4;
            int row = mBase + wm + mt * 16 + gr + (odd ? 8 : 0);
            float xi = iv + sbias[nn + 0];
            float xf = fv + sbias[nn + 1];
            float xg = gv + sbias[nn + 2];
            float xo = ov + sbias[nn + 3];
            if (auxin) {
                float4 xv = *(const float4*)(auxin + (size_t)row * G4H + nBase + nn);
                xi += xv.x; xf += xv.y; xg += xv.z; xo += xv.w;
            }
            float gi = sigm(xi), gf = sigm(xf), gg = tanh_f(xg), go = sigm(xo);
            int unit = (nBase + nn) >> 2;
            size_t idx = (size_t)row * HDIM + unit;
            float cn = gf * cbuf[idx] + gi * gg;
            cbuf[idx] = cn;
            float hn = go * tanh_f(cn);
            f16 hv = __float2half(hn);
            H[idx] = hv;
            if (hist) hist[idx] = hv;
        }
    }
}

// single-layer wrapper (MODE 0)
__global__ void __launch_bounds__(256, 2)
gemm_lstm(const f16* __restrict__ A1, int s1, int nA,
          const f16* __restrict__ A2, int nB,
          const f16* __restrict__ W1, int w1s,
          const f16* __restrict__ W2,
          const float* __restrict__ bias,
          const float* __restrict__ auxin,
          float* __restrict__ cbuf, f16* __restrict__ H,
          f16* __restrict__ hist)
{
    extern __shared__ __align__(1024) char smem[];
    gemm_body<0>(smem, A1, s1, nA, A2, nB, W1, w1s, W2, bias, auxin, nullptr,
                 cbuf, H, hist, blockIdx.y * 128, blockIdx.x * 128);
}

// encoding merged: M(s) = { L2(s-1) [y<8], L1(s) [y>=8] }, s = 1..63
__global__ void __launch_bounds__(256, 2)
gemm_merged(const f16* __restrict__ h1rd,     // h1(s-1)
            const f16* __restrict__ h2rd,     // h2(s-2)
            f16* __restrict__ h2wr,           // h2(s-1) out
            f16* __restrict__ hist,           // slot s-1
            const f16* __restrict__ xs,       // x(s)
            f16* __restrict__ h1wr)           // h1(s) out
{
    extern __shared__ __align__(1024) char smem[];
    const int nBase = blockIdx.x * 128;
    if (blockIdx.y < 8) {
        gemm_body<0>(smem, h1rd, HDIM, 16, h2rd, 16, g_wih2, HDIM, g_whh2,
                     g_bias2, nullptr, nullptr, g_c2, h2wr, hist, blockIdx.y * 128, nBase);
    } else {
        gemm_body<0>(smem, xs, TSEQ * IDIM, 1, h1rd, 16, g_wih1, IDIM, g_whh1,
                     g_bias1, nullptr, nullptr, g_c1, h1wr, nullptr, (blockIdx.y - 8) * 128, nBase);
    }
}

// future merged: M_f(s) = { L2(s-1) [y<8], L1a(s) = h1(s-1)@whh1 -> g_gates [y>=8] }
__global__ void __launch_bounds__(256, 2)
gemm_merged_f(const f16* __restrict__ h1rd,   // h1(s-1)
              const f16* __restrict__ h2rd,   // h2(s-2)
              f16* __restrict__ h2wr,         // h2(s-1) out
              f16* __restrict__ hist)
{
    extern __shared__ __align__(1024) char smem[];
    const int nBase = blockIdx.x * 128;
    if (blockIdx.y < 8) {
        gemm_body<0>(smem, h1rd, HDIM, 16, h2rd, 16, g_wih2, HDIM, g_whh2,
                     g_bias2, nullptr, nullptr, g_c2, h2wr, hist, blockIdx.y * 128, nBase);
    } else {
        gemm_body<1>(smem, h1rd, HDIM, 16, nullptr, 0, g_whh1, HDIM, nullptr,
                     nullptr, nullptr, g_gates, nullptr, nullptr, nullptr,
                     (blockIdx.y - 8) * 128, nBase);
    }
}

// L1b(s): fb-chunk GEMM + gates partials + LSTM epilogue
__global__ void __launch_bounds__(256, 2)
gemm_l1b(f16* __restrict__ h1wr)
{
    extern __shared__ __align__(1024) char smem[];
    gemm_body<0>(smem, g_fb, IDIM, 1, nullptr, 0, g_wih1, IDIM, nullptr,
                 g_bias1, g_gates, nullptr, g_c1, h1wr, nullptr,
                 blockIdx.y * 128, blockIdx.x * 128);
}

// ---------------- batched head kernel: tile 128(M) x 64(N) ----------------
#define HSTAGE 24576   // A 16K | W 8K

__global__ void __launch_bounds__(256, 2)
gemm_head(const f16* __restrict__ A, const f16* __restrict__ Wl,
          const float* __restrict__ bias, float* __restrict__ outp)
{
    extern __shared__ __align__(1024) char smem[];
    const int tid = threadIdx.x;
    const size_t mBase = (size_t)blockIdx.y * 128;
    const uint32_t sb = smem_u32(smem);

    float* sbias = (float*)(smem + 3 * HSTAGE);
    if (tid < 64) sbias[tid] = bias[tid];

    auto load_chunk = [&](int c, int st) {
        uint32_t base = sb + st * HSTAGE;
        const f16* Ap = A + c * 64;
        const f16* Wp = Wl + c * 64;
        #pragma unroll
        for (int j = 0; j < 4; ++j) {
            int o = tid + j * 256; int row = o >> 3; int eo = (o & 7) * 8;
            uint32_t boff = SWZ(row * 128 + eo * 2);
            cp16(base + boff, Ap + (mBase + row) * (size_t)HDIM + eo);
        }
        #pragma unroll
        for (int j = 0; j < 2; ++j) {
            int o = tid + j * 256; int row = o >> 3; int eo = (o & 7) * 8;
            uint32_t boff = SWZ(row * 128 + eo * 2);
            cp16(base + 16384 + boff, Wp + (size_t)row * HDIM + eo);
        }
        cp_commit();
    };

    const int w = tid >> 5, l = tid & 31;
    const int wm = (w & 3) * 32, wn = (w >> 2) * 32;

    float acc[2][4][4];
    #pragma unroll
    for (int mt = 0; mt < 2; ++mt)
        #pragma unroll
        for (int nt = 0; nt < 4; ++nt)
            #pragma unroll
            for (int j = 0; j < 4; ++j) acc[mt][nt][j] = 0.f;

    load_chunk(0, 0);
    load_chunk(1, 1);

    uint32_t aB[2], wB[2];
    {
        const int aColSub = (l >> 4) << 4;
        #pragma unroll
        for (int mt = 0; mt < 2; ++mt)
            aB[mt] = SWZ((uint32_t)(((wm + mt * 16 + (l & 15)) << 7) + aColSub));
        const int wColSub = ((l >> 3) & 1) << 4;
        #pragma unroll
        for (int ng = 0; ng < 2; ++ng)
            wB[ng] = SWZ((uint32_t)(((wn + ng * 16 + (l & 7) + (((l >> 4) & 1) << 3)) << 7) + wColSub));
    }

    const int C = 16;
    for (int c = 0; c < C; ++c) {
        const int st = c % 3;
        cp_wait<1>();
        __syncthreads();

        if (c + 2 < C) load_chunk(c + 2, (c + 2) % 3);
        else cp_commit();

        const uint32_t bA = sb + st * HSTAGE;
        const uint32_t bW = bA + 16384;

        #pragma unroll
        for (int ks = 0; ks < 4; ++ks) {
            const uint32_t kx = (uint32_t)(ks << 5);
            uint32_t af[2][4], wf[2][4];
            #pragma unroll
            for (int mt = 0; mt < 2; ++mt) ldsm4(af[mt], bA + (aB[mt] ^ kx));
            #pragma unroll
            for (int ng = 0; ng < 2; ++ng) ldsm4(wf[ng], bW + (wB[ng] ^ kx));
            #pragma unroll
            for (int mt = 0; mt < 2; ++mt) {
                #pragma unroll
                for (int ng = 0; ng < 2; ++ng) {
                    mma16816(acc[mt][ng * 2],     af[mt], wf[ng][0], wf[ng][1]);
                    mma16816(acc[mt][ng * 2 + 1], af[mt], wf[ng][2], wf[ng][3]);
                }
            }
        }
    }

    #pragma unroll
    for (int mt = 0; mt < 2; ++mt) {
        #pragma unroll
        for (int nt = 0; nt < 4; ++nt) {
            int col = wn + nt * 8 + 2 * (l & 3);
            size_t r0 = mBase + wm + mt * 16 + (l >> 2);
            size_t r1 = r0 + 8;
            int stp = (int)(r0 >> 10);
            if (stp == 63) stp = 79;
            float v0 = acc[mt][nt][0] + sbias[col];
            float v1 = acc[mt][nt][1] + sbias[col + 1];
            float v2 = acc[mt][nt][2] + sbias[col];
            float v3 = acc[mt][nt][3] + sbias[col + 1];
            float* p0 = outp + (r0 & 1023) * OUT_STRIDE + (size_t)stp * IDIM + col;
            float* p1 = outp + (r1 & 1023) * OUT_STRIDE + (size_t)stp * IDIM + col;
            p0[0] = v0; p0[1] = v1;
            p1[0] = v2; p1[1] = v3;
        }
    }
}

// ---------------- inline head (steps 63..78): fp32 split-K ----------------
__global__ __launch_bounds__(256)
void lin_stage1_kernel(const f16* __restrict__ H, const float* __restrict__ Wlin) {
    __shared__ float Hs[16][68];
    __shared__ float Ws[16][68];

    const int tid = threadIdx.x;
    const int mBase = blockIdx.x * 64;
    const int ks = blockIdx.y;
    const int kBeg = ks * 128;

    const int lr = tid >> 2;
    const int lc = (tid & 3) << 2;
    const int tx = tid & 15;
    const int ty = tid >> 4;

    float acc[4][4];
    #pragma unroll
    for (int i = 0; i < 4; ++i)
        #pragma unroll
        for (int j = 0; j < 4; ++j) acc[i][j] = 0.f;

    for (int k0 = kBeg; k0 < kBeg + 128; k0 += 16) {
        size_t hoff = (size_t)(mBase + lr) * HDIM + k0 + lc;
        const __half2* ph = (const __half2*)(H + hoff);
        float2 h0 = __half22float2(ph[0]);
        float2 h1 = __half22float2(ph[1]);
        Hs[lc + 0][lr] = h0.x; Hs[lc + 1][lr] = h0.y;
        Hs[lc + 2][lr] = h1.x; Hs[lc + 3][lr] = h1.y;
        float4 wv = *reinterpret_cast<const float4*>(&Wlin[(size_t)lr * HDIM + k0 + lc]);
        Ws[lc + 0][lr] = wv.x; Ws[lc + 1][lr] = wv.y;
        Ws[lc + 2][lr] = wv.z; Ws[lc + 3][lr] = wv.w;
        __syncthreads();

        #pragma unroll
        for (int kk = 0; kk < 16; ++kk) {
            float a[4], wv2[4];
            #pragma unroll
            for (int i = 0; i < 4; ++i) a[i] = Hs[kk][ty * 4 + i];
            #pragma unroll
            for (int j = 0; j < 4; ++j) wv2[j] = Ws[kk][tx * 4 + j];
            #pragma unroll
            for (int i = 0; i < 4; ++i)
                #pragma unroll
                for (int j = 0; j < 4; ++j)
                    acc[i][j] = fmaf(a[i], wv2[j], acc[i][j]);
        }
        __syncthreads();
    }

    #pragma unroll
    for (int i = 0; i < 4; ++i) {
        int m = mBase + ty * 4 + i;
        #pragma unroll
        for (int j = 0; j < 4; ++j) {
            int n = tx * 4 + j;
            g_part[(size_t)ks * (BSZ * IDIM) + m * IDIM + n] = acc[i][j];
        }
    }
}

__global__ void lin_stage2_kernel(const float* __restrict__ blin,
                                  float* __restrict__ outp) {
    int idx = blockIdx.x * blockDim.x + threadIdx.x;
    int m = idx >> 6;
    int n = idx & 63;
    float s = blin[n];
    #pragma unroll
    for (int ks = 0; ks < 8; ++ks) s += g_part[ks * (BSZ * IDIM) + idx];
    outp[(size_t)m * OUT_STRIDE + n] = s;
    g_fb[idx] = __float2half(s);
}

// ---------------- host launch ----------------
extern "C" void kernel_launch(void* const* d_in, const int* in_sizes, int n_in,
                              void* d_out, int out_size) {
    const float* x     = (const float*)d_in[0];
    const float* W_ih1 = (const float*)d_in[1];
    const float* W_hh1 = (const float*)d_in[2];
    const float* b_ih1 = (const float*)d_in[3];
    const float* b_hh1 = (const float*)d_in[4];
    const float* W_ih2 = (const float*)d_in[5];
    const float* W_hh2 = (const float*)d_in[6];
    const float* b_ih2 = (const float*)d_in[7];
    const float* b_hh2 = (const float*)d_in[8];
    const float* W_lin = (const float*)d_in[9];
    const float* b_lin = (const float*)d_in[10];
    float* out = (float*)d_out;

    void *wih1, *whh1, *wih2, *whh2, *wlinp, *xh, *h1, *h2, *h2hist, *c1, *c2, *fb;
    void *bias1, *bias2, *blinp;
    cudaGetSymbolAddress(&wih1, g_wih1);   cudaGetSymbolAddress(&whh1, g_whh1);
    cudaGetSymbolAddress(&wih2, g_wih2);   cudaGetSymbolAddress(&whh2, g_whh2);
    cudaGetSymbolAddress(&wlinp, g_wlinp);
    cudaGetSymbolAddress(&xh, g_x);
    cudaGetSymbolAddress(&h1, g_h1);       cudaGetSymbolAddress(&h2, g_h2);
    cudaGetSymbolAddress(&h2hist, g_h2hist);
    cudaGetSymbolAddress(&c1, g_c1);       cudaGetSymbolAddress(&c2, g_c2);
    cudaGetSymbolAddress(&fb, g_fb);
    cudaGetSymbolAddress(&bias1, g_bias1); cudaGetSymbolAddress(&bias2, g_bias2);
    cudaGetSymbolAddress(&blinp, g_blinp);

    f16* H1[2] = { (f16*)h1, (f16*)h1 + BSZ * HDIM };
    f16* H2[2] = { (f16*)h2, (f16*)h2 + BSZ * HDIM };
    f16* HIST  = (f16*)h2hist;

    constexpr int SMEM_MAIN = 3 * STAGE + 512;    // 98816
    constexpr int SMEM_HEAD = 3 * HSTAGE + 512;   // 74240
    cudaFuncSetAttribute(gemm_lstm,     cudaFuncAttributeMaxDynamicSharedMemorySize, SMEM_MAIN);
    cudaFuncSetAttribute(gemm_merged,   cudaFuncAttributeMaxDynamicSharedMemorySize, SMEM_MAIN);
    cudaFuncSetAttribute(gemm_merged_f, cudaFuncAttributeMaxDynamicSharedMemorySize, SMEM_MAIN);
    cudaFuncSetAttribute(gemm_l1b,      cudaFuncAttributeMaxDynamicSharedMemorySize, SMEM_MAIN);
    cudaFuncSetAttribute(gemm_head,     cudaFuncAttributeMaxDynamicSharedMemorySize, SMEM_HEAD);

    // ---- prepasses (3 launches) ----
    prepW<<<(3 * QW1 + QIH1 + QLIN) / 256, 256>>>(W_hh1, W_ih2, W_hh2, W_ih1, W_lin);
    prepX<<<(BSZ * TSEQ * IDIM / 4) / 256, 256>>>(x);
    prepMisc<<<(BSZ * HDIM) / 256, 256>>>(b_ih1, b_hh1, b_ih2, b_hh2, b_lin);

    const dim3 gL(G4H / 128, BSZ / 128);   // (32, 8)
    const dim3 gM(G4H / 128, 16);          // (32, 16) merged

    // L1(0): reads x(0), h1(-1)=zeros (H1[0]); writes H1[1]
    gemm_lstm<<<gL, 256, SMEM_MAIN>>>(
        (const f16*)xh, TSEQ * IDIM, 1,
        H1[0], 16,
        (const f16*)wih1, IDIM, (const f16*)whh1,
        (const float*)bias1, nullptr, (float*)c1, H1[1], nullptr);

    // encoding phase merged: M(s) = { L2(s-1), L1(s) }, s = 1..63
    for (int s = 1; s <= 63; ++s) {
        int p = s & 1;
        gemm_merged<<<gM, 256, SMEM_MAIN>>>(
            H1[p],                // h1(s-1)
            H2[p ^ 1],            // h2(s-2)
            H2[p],                // h2(s-1) out
            HIST + (size_t)(s - 1) * BSZ * HDIM,   // slots 0..62
            (const f16*)xh + (size_t)s * IDIM,
            H1[p ^ 1]);           // h1(s) out
    }

    // future phase: s = 64..79
    // M_f(s) = { L2(s-1), L1a(s) }  ->  head(s-1)  ->  L1b(s)
    for (int s = 64; s < NSTEP; ++s) {
        int p = s & 1;
        // L2(s-1) reads h1(s-1)=H1[p], h2(s-2)=H2[p^1]; writes h2(s-1)=H2[p].
        // L1a(s) reads h1(s-1)=H1[p]; writes g_gates.
        gemm_merged_f<<<gM, 256, SMEM_MAIN>>>(H1[p], H2[p ^ 1], H2[p], nullptr);

        // head(s-1): out(s-1) + fb from h2(s-1)
        lin_stage1_kernel<<<dim3(BSZ / 64, 8), 256>>>(H2[p], W_lin);
        lin_stage2_kernel<<<(BSZ * IDIM) / 256, 256>>>(b_lin, out + (size_t)(s - 1) * IDIM);

        // L1b(s): fb chunk + g_gates -> h1(s) = H1[p^1], c1
        gemm_l1b<<<gL, 256, SMEM_MAIN>>>(H1[p ^ 1]);
    }

    // L2(79): reads h1(79)=H1[0] (L1b(79) wrote H1[(79&1)^1]=H1[0]), h2(78)=H2[1];
    // writes h2(79)=H2[0] + hist slot 63 (for out(79) in batched head)
    gemm_lstm<<<gL, 256, SMEM_MAIN>>>(
        H1[0], HDIM, 16,
        H2[1], 16,
        (const f16*)wih2, HDIM, (const f16*)whh2,
        (const float*)bias2, nullptr, (float*)c2, H2[0],
        HIST + (size_t)63 * BSZ * HDIM);

    // batched head: steps 0..62 + 79
    gemm_head<<<dim3(1, HSLOTS * 8), 256, SMEM_HEAD>>>(
        HIST, (const f16*)wlinp, (const float*)blinp, out);
}